// round 16
// baseline (speedup 1.0000x reference)
#include <cuda_runtime.h>
#include <cstdint>
#include <cstddef>

// ---------------- problem constants ----------------
#define NA 200000      // atoms
#define NB 400000      // bonds
#define NM 10000       // molecules
#define AF 133         // atom feature dim
#define BFD 13         // bond feature dim
#define HID 300        // hidden
#define NPAD 320       // padded hidden (5 x 64 N-tiles)
#define NT 5           // N tiles of 64
#define NTASK 12
#define DEPTH 3
#define KP_A 160       // padded K for atom features (133 -> 160)
#define KP_B 32        // padded K for bond features (13 -> 32)
#define KP_H 320       // padded K for hidden (300 -> 320)
#define CAP 64         // bond-bucket capacity per atom
#define CH76 76        // float4 chunks covering cols 0..303 (pad 304+ stays 0)

// All hidden-space buffers are stored in PERMUTED column order:
// within each group of 8 columns, natural k sits at pos = 2*(k&3)+((k>>2)&1)
// (matches mma.sync tf32 fragment pairing so cp.async stages raw 16B chunks).
// All GEMM A/B-feeding values are tf32-pre-rounded (cvt.rna) by producers.

// ---------------- scratch (device globals; no allocation allowed) -------
static __device__ float g_h0 [(size_t)NB * NPAD];   // 512 MB
static __device__ float g_h  [(size_t)NB * NPAD];   // 512 MB
static __device__ float g_Y  [(size_t)NB * NPAD];   // 512 MB (bondproj / Y)
static __device__ float g_am [(size_t)NA * NPAD];   // 256 MB (atomproj / am / tmp)
static __device__ float g_am2[(size_t)NA * NPAD];   // 256 MB
static __device__ float g_faP[(size_t)NA * KP_A];   // 128 MB (packed atom feats)
static __device__ float g_fbP[(size_t)NB * KP_B];   // 51 MB (packed bond feats)
static __device__ float g_mol[(size_t)NM * NPAD];
static __device__ float g_o1 [(size_t)NM * NPAD];
static __device__ float g_WpA[(size_t)NPAD * KP_A];
static __device__ float g_WpB[(size_t)NPAD * KP_B];
static __device__ float g_WpH[(size_t)NPAD * KP_H];
static __device__ float g_Wo1[(size_t)NPAD * KP_A];
static __device__ float g_Wo2[(size_t)NPAD * KP_H];
static __device__ float g_WpR[(size_t)NPAD * KP_H];
static __device__ float g_bO [NPAD];
static __device__ float g_bR [NPAD];
static __device__ int   g_tgt[NB];
static __device__ int   g_cnt[NA];
static __device__ int   g_bkt[(size_t)NA * CAP];    // 51 MB

__device__ __forceinline__ float rndtf(float x) {
    uint32_t r; asm("cvt.rna.tf32.f32 %0, %1;" : "=r"(r) : "f"(x));
    return __uint_as_float(r);
}
__device__ __forceinline__ int permcol(int k) {
    return (k & ~7) | (((k & 3) << 1) | ((k >> 2) & 1));
}
__device__ __forceinline__ int invperm(int p) {
    return (p & ~7) | ((p >> 1) & 3) | (((p & 1) << 2));
}
__device__ __forceinline__ void mma8(float* d, const uint32_t* a, const uint32_t* b) {
    asm volatile(
        "mma.sync.aligned.m16n8k8.row.col.f32.tf32.tf32.f32 "
        "{%0,%1,%2,%3}, {%4,%5,%6,%7}, {%8,%9}, {%0,%1,%2,%3};"
        : "+f"(d[0]), "+f"(d[1]), "+f"(d[2]), "+f"(d[3])
        : "r"(a[0]), "r"(a[1]), "r"(a[2]), "r"(a[3]), "r"(b[0]), "r"(b[1]));
}

// ================= tf32 mma.sync GEMM, cp.async 3-stage pipeline ===========
// C[M x 320] = epi(A @ Wp^T). A [M x KP], Wp [320 x KP]: permuted k-order,
// tf32-pre-rounded. Grid (NT, ceil(M/128)), block 128. CTA 128x64, BK=32;
// 4 warps 2(M)x2(N), warp tile 64x32.
// EPI 0: store rndtf(acc) at permuted cols
// EPI 1: v = relu(acc + addend[r,pc] + bias[col]); atomicAdd accb[ridx[r],pc]
//        for col < 300 (molecule pooling with W_o-split addend)
// EPI 2: store rndtf(relu(acc + bias)) at permuted cols
#define SA 40
static constexpr int ASZ = 128 * SA;
static constexpr int WSZ = 64 * SA;
static constexpr int STG = 3;
static constexpr int SMEM_G = STG * (ASZ + WSZ) * 4;  // 92160 bytes

template <int EPI>
__global__ __launch_bounds__(128, 2) void mma_gemm(
    const float* __restrict__ A, int M, int KP,
    const float* __restrict__ Wp, const float* __restrict__ biasp,
    const int* __restrict__ ridx, const float* __restrict__ addend,
    float* __restrict__ Y, float* __restrict__ accb)
{
    extern __shared__ __align__(16) uint32_t smemu[];

    const int tid  = threadIdx.x;
    const int lane = tid & 31;
    const int wid  = tid >> 5;
    const int warpM = wid >> 1;
    const int warpN = wid & 1;
    const int row0 = blockIdx.y * 128;
    const int col0 = blockIdx.x * 64;
    const int n    = KP >> 5;

    auto issue = [&](int c, int buf) {
        uint32_t* As = smemu + buf * ASZ;
        uint32_t* Ws = smemu + STG * ASZ + buf * WSZ;
        const int koff = c * 32;
#pragma unroll
        for (int t = 0; t < 8; t++) {
            int j = tid + t * 128;
            int row = j >> 3, q = j & 7;
            int rg = row0 + row;
            bool v = rg < M;
            const float* src = A + (size_t)(v ? rg : 0) * KP + koff + q * 4;
            uint32_t d = (uint32_t)__cvta_generic_to_shared(&As[row * SA + q * 4]);
            int sz = v ? 16 : 0;
            asm volatile("cp.async.cg.shared.global [%0], [%1], 16, %2;"
                         :: "r"(d), "l"(src), "r"(sz));
        }
#pragma unroll
        for (int t = 0; t < 4; t++) {
            int j = tid + t * 128;
            int row = j >> 3, q = j & 7;
            const float* src = Wp + (size_t)(col0 + row) * KP + koff + q * 4;
            uint32_t d = (uint32_t)__cvta_generic_to_shared(&Ws[row * SA + q * 4]);
            asm volatile("cp.async.cg.shared.global [%0], [%1], 16, 16;"
                         :: "r"(d), "l"(src));
        }
        asm volatile("cp.async.commit_group;");
    };

    float acc[4][4][4];
#pragma unroll
    for (int i = 0; i < 4; i++)
#pragma unroll
        for (int j = 0; j < 4; j++)
#pragma unroll
            for (int q = 0; q < 4; q++) acc[i][j][q] = 0.f;

    issue(0, 0);
    if (n > 1) issue(1, 1);

    for (int c = 0; c < n; c++) {
        if (c + 1 < n) { asm volatile("cp.async.wait_group 1;"); }
        else           { asm volatile("cp.async.wait_group 0;"); }
        __syncthreads();
        if (c + 2 < n) issue(c + 2, (c + 2) % STG);

        const uint32_t* As = smemu + (c % STG) * ASZ;
        const uint32_t* Ws = smemu + STG * ASZ + (c % STG) * WSZ;
#pragma unroll
        for (int s = 0; s < 4; s++) {
            uint32_t a[4][4], b[4][2];
#pragma unroll
            for (int mf = 0; mf < 4; mf++) {
                int r = warpM * 64 + mf * 16 + (lane >> 2);
                uint2 lo = *reinterpret_cast<const uint2*>(
                    &As[r * SA + s * 8 + 2 * (lane & 3)]);
                uint2 hi = *reinterpret_cast<const uint2*>(
                    &As[(r + 8) * SA + s * 8 + 2 * (lane & 3)]);
                a[mf][0] = lo.x; a[mf][1] = hi.x; a[mf][2] = lo.y; a[mf][3] = hi.y;
            }
#pragma unroll
            for (int nf = 0; nf < 4; nf++) {
                int nn = warpN * 32 + nf * 8 + (lane >> 2);
                uint2 bb = *reinterpret_cast<const uint2*>(
                    &Ws[nn * SA + s * 8 + 2 * (lane & 3)]);
                b[nf][0] = bb.x; b[nf][1] = bb.y;
            }
#pragma unroll
            for (int mf = 0; mf < 4; mf++)
#pragma unroll
                for (int nf = 0; nf < 4; nf++)
                    mma8(acc[mf][nf], a[mf], b[nf]);
        }
    }

    // ---- epilogue (permuted column positions) ----
#pragma unroll
    for (int mf = 0; mf < 4; mf++) {
        int r0 = row0 + warpM * 64 + mf * 16 + (lane >> 2);
        int r1 = r0 + 8;
        bool v0 = r0 < M, v1 = r1 < M;
        int t0 = 0, t1 = 0;
        if (EPI == 1) {
            t0 = v0 ? ridx[r0] : 0;
            t1 = v1 ? ridx[r1] : 0;
        }
#pragma unroll
        for (int nf = 0; nf < 4; nf++) {
            int col = col0 + warpN * 32 + nf * 8 + 2 * (lane & 3);
            int pc0 = permcol(col), pc1 = permcol(col + 1);
            float c0 = acc[mf][nf][0], c1 = acc[mf][nf][1];
            float c2 = acc[mf][nf][2], c3 = acc[mf][nf][3];
            if (EPI == 0) {
                if (v0) {
                    Y[(size_t)r0 * NPAD + pc0] = rndtf(c0);
                    Y[(size_t)r0 * NPAD + pc1] = rndtf(c1);
                }
                if (v1) {
                    Y[(size_t)r1 * NPAD + pc0] = rndtf(c2);
                    Y[(size_t)r1 * NPAD + pc1] = rndtf(c3);
                }
            } else if (EPI == 1) {
                if (col < HID) {
                    float2 bsv = *reinterpret_cast<const float2*>(&biasp[col]);
                    if (v0) {
                        float a0 = addend[(size_t)r0 * NPAD + pc0];
                        float a1 = addend[(size_t)r0 * NPAD + pc1];
                        atomicAdd(accb + (size_t)t0 * NPAD + pc0,
                                  fmaxf(c0 + a0 + bsv.x, 0.f));
                        atomicAdd(accb + (size_t)t0 * NPAD + pc1,
                                  fmaxf(c1 + a1 + bsv.y, 0.f));
                    }
                    if (v1) {
                        float a2 = addend[(size_t)r1 * NPAD + pc0];
                        float a3 = addend[(size_t)r1 * NPAD + pc1];
                        atomicAdd(accb + (size_t)t1 * NPAD + pc0,
                                  fmaxf(c2 + a2 + bsv.x, 0.f));
                        atomicAdd(accb + (size_t)t1 * NPAD + pc1,
                                  fmaxf(c3 + a3 + bsv.y, 0.f));
                    }
                }
            } else { // EPI 2
                float2 bsv = *reinterpret_cast<const float2*>(&biasp[col]);
                c0 = fmaxf(c0 + bsv.x, 0.f); c1 = fmaxf(c1 + bsv.y, 0.f);
                c2 = fmaxf(c2 + bsv.x, 0.f); c3 = fmaxf(c3 + bsv.y, 0.f);
                if (v0) {
                    Y[(size_t)r0 * NPAD + pc0] = rndtf(c0);
                    Y[(size_t)r0 * NPAD + pc1] = rndtf(c1);
                }
                if (v1) {
                    Y[(size_t)r1 * NPAD + pc0] = rndtf(c2);
                    Y[(size_t)r1 * NPAD + pc1] = rndtf(c3);
                }
            }
        }
    }
}

// --------- index prep -------------------------------------------------------
__global__ void tgt_kernel(const int* __restrict__ b2a,
                           const int* __restrict__ b2revb,
                           int* __restrict__ tgt)
{
    int b = blockIdx.x * blockDim.x + threadIdx.x;
    if (b < NB) tgt[b] = b2a[b2revb[b]];
}

__global__ void bucket_kernel(const int* __restrict__ tgt,
                              int* __restrict__ cnt, int* __restrict__ bkt)
{
    int b = blockIdx.x * blockDim.x + threadIdx.x;
    if (b >= NB) return;
    int a = tgt[b];
    int s = atomicAdd(&cnt[a], 1);
    if (s < CAP) bkt[(size_t)a * CAP + s] = b;
}

// --------- gather (rounded): out[a] = rnd(sum over bucketed bonds of X[b]) -
__global__ void gather_kernel(const float* __restrict__ X,
                              const int* __restrict__ cnt,
                              const int* __restrict__ bkt,
                              float* __restrict__ out)
{
    int idx = blockIdx.x * blockDim.x + threadIdx.x;
    if (idx >= NA * CH76) return;
    int a = idx / CH76, c = idx % CH76;
    int n = cnt[a]; if (n > CAP) n = CAP;
    const int* bl = bkt + (size_t)a * CAP;
    float4 s = make_float4(0.f, 0.f, 0.f, 0.f);
    for (int j = 0; j < n; j++) {
        float4 v = reinterpret_cast<const float4*>(X + (size_t)bl[j] * NPAD)[c];
        s.x += v.x; s.y += v.y; s.z += v.z; s.w += v.w;
    }
    float4 r = make_float4(rndtf(s.x), rndtf(s.y), rndtf(s.z), rndtf(s.w));
    reinterpret_cast<float4*>(out + (size_t)a * NPAD)[c] = r;
}

// --------- h0 init: h0[b] = rnd(relu(atomproj[b2a[b]] + bondproj[b])) ------
__global__ void init_kernel(const float* __restrict__ ap,
                            const float* __restrict__ bp,
                            const int* __restrict__ b2a,
                            float* __restrict__ h0)
{
    size_t tid = (size_t)blockIdx.x * blockDim.x + threadIdx.x;
    if (tid >= (size_t)NB * CH76) return;
    int bond = (int)(tid / CH76);
    int c = (int)(tid % CH76);
    int a = b2a[bond];
    float4 va = reinterpret_cast<const float4*>(ap + (size_t)a    * NPAD)[c];
    float4 vb = reinterpret_cast<const float4*>(bp + (size_t)bond * NPAD)[c];
    float4 r;
    r.x = rndtf(fmaxf(va.x + vb.x, 0.f));
    r.y = rndtf(fmaxf(va.y + vb.y, 0.f));
    r.z = rndtf(fmaxf(va.z + vb.z, 0.f));
    r.w = rndtf(fmaxf(va.w + vb.w, 0.f));
    reinterpret_cast<float4*>(h0 + (size_t)bond * NPAD)[c] = r;
}

// --------- feature packs (permuted + rounded) ------------------------------
__global__ void pack_faP(const float* __restrict__ fa, float* __restrict__ dst)
{
    size_t idx = (size_t)blockIdx.x * blockDim.x + threadIdx.x;
    if (idx >= (size_t)NA * KP_A) return;
    int a = (int)(idx / KP_A), k = (int)(idx % KP_A);
    float v = (k < AF) ? fa[(size_t)a * AF + k] : 0.f;
    dst[(size_t)a * KP_A + permcol(k)] = rndtf(v);
}

__global__ void pack_fbP(const float* __restrict__ fb, float* __restrict__ dst)
{
    size_t idx = (size_t)blockIdx.x * blockDim.x + threadIdx.x;
    if (idx >= (size_t)NB * KP_B) return;
    int b = (int)(idx / KP_B), k = (int)(idx % KP_B);
    float v = (k < BFD) ? fb[(size_t)b * BFD + k] : 0.f;
    dst[(size_t)b * KP_B + permcol(k)] = rndtf(v);
}

// --------- weight pad: src[rows x src_stride], cols [col0, col0+ncols) -----
__global__ void pad_W2(const float* __restrict__ src, int rows, int src_stride,
                       int col0, int ncols, int KP, float* __restrict__ dst)
{
    int idx = blockIdx.x * blockDim.x + threadIdx.x;
    if (idx >= NPAD * KP) return;
    int rp = idx / KP, k = idx % KP;
    float v = (rp < rows && k < ncols) ? src[(size_t)rp * src_stride + col0 + k] : 0.f;
    dst[(size_t)rp * KP + permcol(k)] = rndtf(v);
}

__global__ void pad_bias(const float* __restrict__ src, float* __restrict__ dst)
{
    int c = threadIdx.x + blockIdx.x * blockDim.x;
    if (c < NPAD) dst[c] = (c < HID) ? src[c] : 0.f;   // natural order
}

__global__ void round_kernel(float* __restrict__ x, int nelem)
{
    int i = blockIdx.x * blockDim.x + threadIdx.x;
    if (i < nelem) x[i] = rndtf(x[i]);
}

// --------- combine: h = rnd(relu(h0 + am[b2a] - Y[b2revb])) ----------------
__global__ void combine_kernel(const float* __restrict__ h0,
                               const float* __restrict__ amsg,
                               const float* __restrict__ Y,
                               const int* __restrict__ b2a,
                               const int* __restrict__ b2revb,
                               float* __restrict__ hout)
{
    size_t tid = (size_t)blockIdx.x * blockDim.x + threadIdx.x;
    if (tid >= (size_t)NB * CH76) return;
    int bond = (int)(tid / CH76);
    int c = (int)(tid % CH76);
    int a  = b2a[bond];
    int rb = b2revb[bond];
    float4 v0 = reinterpret_cast<const float4*>(h0   + (size_t)bond * NPAD)[c];
    float4 va = reinterpret_cast<const float4*>(amsg + (size_t)a    * NPAD)[c];
    float4 vy = reinterpret_cast<const float4*>(Y    + (size_t)rb   * NPAD)[c];
    float4 r;
    r.x = rndtf(fmaxf(v0.x + va.x - vy.x, 0.f));
    r.y = rndtf(fmaxf(v0.y + va.y - vy.y, 0.f));
    r.z = rndtf(fmaxf(v0.z + va.z - vy.z, 0.f));
    r.w = rndtf(fmaxf(v0.w + va.w - vy.w, 0.f));
    reinterpret_cast<float4*>(hout + (size_t)bond * NPAD)[c] = r;
}

// --------- final logits (o1 permuted; un-permute via invperm) --------------
__global__ void logits_kernel(const float* __restrict__ X,
                              const float* __restrict__ W2,
                              const float* __restrict__ b2,
                              float* __restrict__ out)
{
    int warp = (blockIdx.x * blockDim.x + threadIdx.x) >> 5;
    int lane = threadIdx.x & 31;
    if (warp >= NM) return;
    const float* x = X + (size_t)warp * NPAD;
    float acc[NTASK];
#pragma unroll
    for (int t = 0; t < NTASK; t++) acc[t] = 0.f;
    for (int p = lane; p < NPAD; p += 32) {
        int k = invperm(p);
        if (k >= HID) continue;
        float xv = x[p];
#pragma unroll
        for (int t = 0; t < NTASK; t++)
            acc[t] = fmaf(xv, W2[t * HID + k], acc[t]);
    }
#pragma unroll
    for (int t = 0; t < NTASK; t++) {
        float v = acc[t];
#pragma unroll
        for (int off = 16; off; off >>= 1)
            v += __shfl_down_sync(0xffffffffu, v, off);
        if (lane == 0) out[warp * NTASK + t] = v + b2[t];
    }
}

// ---------------- driver ----------------
extern "C" void kernel_launch(void* const* d_in, const int* in_sizes, int n_in,
                              void* d_out, int out_size)
{
    const float* f_atoms = (const float*)d_in[0];
    const float* f_bonds = (const float*)d_in[1];
    const int*   b2a     = (const int*)d_in[2];
    const int*   b2revb  = (const int*)d_in[3];
    const int*   mol_ids = (const int*)d_in[4];
    const float* W_i     = (const float*)d_in[5];
    const float* W_h     = (const float*)d_in[6];
    const float* W_o     = (const float*)d_in[7];
    const float* b_o     = (const float*)d_in[8];
    const float* W_r1    = (const float*)d_in[9];
    const float* b_r1    = (const float*)d_in[10];
    const float* W_r2    = (const float*)d_in[11];
    const float* b_r2    = (const float*)d_in[12];
    float* out = (float*)d_out;

    float *h0, *h, *Y, *am, *am2, *faP, *fbP, *mol, *o1;
    float *WpA, *WpB, *WpH, *Wo1, *Wo2, *WpR, *bO, *bR;
    int *tgt, *cnt, *bkt;
    cudaGetSymbolAddress((void**)&h0,  g_h0);
    cudaGetSymbolAddress((void**)&h,   g_h);
    cudaGetSymbolAddress((void**)&Y,   g_Y);
    cudaGetSymbolAddress((void**)&am,  g_am);
    cudaGetSymbolAddress((void**)&am2, g_am2);
    cudaGetSymbolAddress((void**)&faP, g_faP);
    cudaGetSymbolAddress((void**)&fbP, g_fbP);
    cudaGetSymbolAddress((void**)&mol, g_mol);
    cudaGetSymbolAddress((void**)&o1,  g_o1);
    cudaGetSymbolAddress((void**)&WpA, g_WpA);
    cudaGetSymbolAddress((void**)&WpB, g_WpB);
    cudaGetSymbolAddress((void**)&WpH, g_WpH);
    cudaGetSymbolAddress((void**)&Wo1, g_Wo1);
    cudaGetSymbolAddress((void**)&Wo2, g_Wo2);
    cudaGetSymbolAddress((void**)&WpR, g_WpR);
    cudaGetSymbolAddress((void**)&bO,  g_bO);
    cudaGetSymbolAddress((void**)&bR,  g_bR);
    cudaGetSymbolAddress((void**)&tgt, g_tgt);
    cudaGetSymbolAddress((void**)&cnt, g_cnt);
    cudaGetSymbolAddress((void**)&bkt, g_bkt);

    cudaFuncSetAttribute(mma_gemm<0>, cudaFuncAttributeMaxDynamicSharedMemorySize, SMEM_G);
    cudaFuncSetAttribute(mma_gemm<1>, cudaFuncAttributeMaxDynamicSharedMemorySize, SMEM_G);
    cudaFuncSetAttribute(mma_gemm<2>, cudaFuncAttributeMaxDynamicSharedMemorySize, SMEM_G);

    const dim3 blk(256);
    const dim3 gblk(128);

    // 0) indices + bucket-CSR + packed features + padded weights/biases
    tgt_kernel<<<(NB + 255) / 256, blk>>>(b2a, b2revb, tgt);
    cudaMemsetAsync(cnt, 0, NA * sizeof(int));
    bucket_kernel<<<(NB + 255) / 256, blk>>>(tgt, cnt, bkt);
    pack_faP<<<(unsigned)(((size_t)NA * KP_A + 255) / 256), blk>>>(f_atoms, faP);
    pack_fbP<<<(unsigned)(((size_t)NB * KP_B + 255) / 256), blk>>>(f_bonds, fbP);
    pad_W2<<<(NPAD * KP_A + 255) / 256, blk>>>(W_i,  HID, AF + BFD, 0,   AF,  KP_A, WpA);
    pad_W2<<<(NPAD * KP_B + 255) / 256, blk>>>(W_i,  HID, AF + BFD, AF,  BFD, KP_B, WpB);
    pad_W2<<<(NPAD * KP_H + 255) / 256, blk>>>(W_h,  HID, HID,      0,   HID, KP_H, WpH);
    pad_W2<<<(NPAD * KP_A + 255) / 256, blk>>>(W_o,  HID, AF + HID, 0,   AF,  KP_A, Wo1);
    pad_W2<<<(NPAD * KP_H + 255) / 256, blk>>>(W_o,  HID, AF + HID, AF,  HID, KP_H, Wo2);
    pad_W2<<<(NPAD * KP_H + 255) / 256, blk>>>(W_r1, HID, HID,      0,   HID, KP_H, WpR);
    pad_bias<<<2, 256>>>(b_o,  bO);
    pad_bias<<<2, 256>>>(b_r1, bR);

    // 1) h0 init via concat-split (linearity):
    //    atomproj = faP @ WpA^T (atoms);  bondproj = fbP @ WpB^T (bonds);
    //    h0[b] = rnd(relu(atomproj[b2a[b]] + bondproj[b]))
    {
        dim3 ga(NT, (NA + 127) / 128);
        mma_gemm<0><<<ga, gblk, SMEM_G>>>(faP, NA, KP_A, WpA, nullptr, nullptr,
                                          nullptr, am, nullptr);
        dim3 gb(NT, NB / 128);
        mma_gemm<0><<<gb, gblk, SMEM_G>>>(fbP, NB, KP_B, WpB, nullptr, nullptr,
                                          nullptr, Y, nullptr);
        unsigned iB = (unsigned)(((size_t)NB * CH76 + 255) / 256);
        init_kernel<<<iB, blk>>>(am, Y, b2a, h0);
    }

    // 2) DEPTH message rounds:
    //    Y = h @ W_h^T;  am = rnd(bucket-gather(Y, tgt));
    //    h' = rnd(relu(h0 + am[b2a] - Y[b2revb]))
    const unsigned combB = (unsigned)(((size_t)NB * CH76 + 255) / 256);
    const unsigned gatB  = (unsigned)((NA * CH76 + 255) / 256);
    float* h_cur = h0;
    for (int d = 0; d < DEPTH; d++) {
        dim3 g(NT, NB / 128);
        mma_gemm<0><<<g, gblk, SMEM_G>>>(h_cur, NB, KP_H, WpH, nullptr, nullptr,
                                         nullptr, Y, nullptr);
        gather_kernel<<<gatB, blk>>>(Y, cnt, bkt, am);
        combine_kernel<<<combB, blk>>>(h0, am, Y, b2a, b2revb, h);
        h_cur = h;
    }

    // 3) final bond->atom aggregation of h
    gather_kernel<<<gatB, blk>>>(h_cur, cnt, bkt, am2);

    // 4) W_o readout via concat-split, fused with molecule pooling:
    //    tmp(am) = faP @ Wo1^T;  mol += relu(am2@Wo2^T + tmp + b_o) by mol_ids
    {
        dim3 g(NT, (NA + 127) / 128);
        mma_gemm<0><<<g, gblk, SMEM_G>>>(faP, NA, KP_A, Wo1, nullptr, nullptr,
                                         nullptr, am, nullptr);
        cudaMemsetAsync(mol, 0, (size_t)NM * NPAD * sizeof(float));
        mma_gemm<1><<<g, gblk, SMEM_G>>>(am2, NA, KP_H, Wo2, bO, mol_ids,
                                         am, nullptr, mol);
    }

    // 5) readout head
    round_kernel<<<(NM * NPAD + 255) / 256, blk>>>(mol, NM * NPAD);
    {
        dim3 g(NT, (NM + 127) / 128);
        mma_gemm<2><<<g, gblk, SMEM_G>>>(mol, NM, KP_H, WpR, bR, nullptr,
                                         nullptr, o1, nullptr);
    }
    logits_kernel<<<(NM * 32 + 255) / 256, blk>>>(o1, W_r2, b_r2, out);
}

// round 17
// speedup vs baseline: 1.0316x; 1.0316x over previous
#include <cuda_runtime.h>
#include <cstdint>
#include <cstddef>

// ---------------- problem constants ----------------
#define NA 200000      // atoms
#define NB 400000      // bonds
#define NM 10000       // molecules
#define AF 133         // atom feature dim
#define BFD 13         // bond feature dim
#define HID 300        // hidden
#define NPAD 320       // padded hidden (5 x 64 N-tiles)
#define NT 5           // N tiles of 64
#define NTASK 12
#define DEPTH 3
#define KP_I 160       // padded K for h0 init  (146 -> 160)
#define KP_A 160       // padded K for atom features (133 -> 160)
#define KP_H 320       // padded K for hidden (300 -> 320)
#define CAP 64         // bond-bucket capacity per atom
#define CH76 76        // float4 chunks covering cols 0..303 (pad 304+ stays 0)

// All hidden-space buffers are stored in PERMUTED column order:
// within each group of 8 columns, natural k sits at pos = 2*(k&3)+((k>>2)&1)
// (matches mma.sync tf32 fragment pairing so cp.async stages raw 16B chunks).
// All GEMM A/B-feeding values are tf32-pre-rounded (cvt.rna) by producers.

// ---------------- scratch (device globals; no allocation allowed) -------
static __device__ float g_h0 [(size_t)NB * NPAD];   // 512 MB
static __device__ float g_h  [(size_t)NB * NPAD];   // 512 MB (h; also h0-A pack)
static __device__ float g_Y  [(size_t)NB * NPAD];   // 512 MB
static __device__ float g_am [(size_t)NA * NPAD];   // 256 MB (am / W_o tmp)
static __device__ float g_am2[(size_t)NA * NPAD];   // 256 MB
static __device__ float g_faP[(size_t)NA * KP_A];   // 128 MB (packed atom feats)
static __device__ float g_mol[(size_t)NM * NPAD];
static __device__ float g_o1 [(size_t)NM * NPAD];
static __device__ float g_WpI[(size_t)NPAD * KP_I];
static __device__ float g_WpH[(size_t)NPAD * KP_H];
static __device__ float g_Wo1[(size_t)NPAD * KP_A];
static __device__ float g_Wo2[(size_t)NPAD * KP_H];
static __device__ float g_WpR[(size_t)NPAD * KP_H];
static __device__ float g_bO [NPAD];
static __device__ float g_bR [NPAD];
static __device__ float g_zb [NPAD];                // stays zero (never written)
static __device__ int   g_tgt[NB];
static __device__ int   g_cnt[NA];
static __device__ int   g_bkt[(size_t)NA * CAP];    // 51 MB

__device__ __forceinline__ float rndtf(float x) {
    uint32_t r; asm("cvt.rna.tf32.f32 %0, %1;" : "=r"(r) : "f"(x));
    return __uint_as_float(r);
}
__device__ __forceinline__ int permcol(int k) {
    return (k & ~7) | (((k & 3) << 1) | ((k >> 2) & 1));
}
__device__ __forceinline__ int invperm(int p) {
    return (p & ~7) | ((p >> 1) & 3) | (((p & 1) << 2));
}
__device__ __forceinline__ void mma8(float* d, const uint32_t* a, const uint32_t* b) {
    asm volatile(
        "mma.sync.aligned.m16n8k8.row.col.f32.tf32.tf32.f32 "
        "{%0,%1,%2,%3}, {%4,%5,%6,%7}, {%8,%9}, {%0,%1,%2,%3};"
        : "+f"(d[0]), "+f"(d[1]), "+f"(d[2]), "+f"(d[3])
        : "r"(a[0]), "r"(a[1]), "r"(a[2]), "r"(a[3]), "r"(b[0]), "r"(b[1]));
}

// ================= tf32 mma.sync GEMM, cp.async 3-stage pipeline ===========
// C[M x 320] = epi(A @ Wp^T). A [M x KP], Wp [320 x KP]: permuted k-order,
// tf32-pre-rounded. Grid (NT, ceil(M/128)), block 128. CTA 128x64, BK=32;
// 4 warps 2(M)x2(N), warp tile 64x32.
// EPI 0: store rndtf(acc) at permuted cols
// EPI 1: v = relu(acc + addend[r,pc] + bias[col]); atomicAdd accb[ridx[r],pc]
//        for col < 300 (molecule pooling with W_o-split addend)
// EPI 2: store rndtf(relu(acc + bias)) at permuted cols
#define SA 40
static constexpr int ASZ = 128 * SA;
static constexpr int WSZ = 64 * SA;
static constexpr int STG = 3;
static constexpr int SMEM_G = STG * (ASZ + WSZ) * 4;  // 92160 bytes

template <int EPI>
__global__ __launch_bounds__(128, 2) void mma_gemm(
    const float* __restrict__ A, int M, int KP,
    const float* __restrict__ Wp, const float* __restrict__ biasp,
    const int* __restrict__ ridx, const float* __restrict__ addend,
    float* __restrict__ Y, float* __restrict__ accb)
{
    extern __shared__ __align__(16) uint32_t smemu[];

    const int tid  = threadIdx.x;
    const int lane = tid & 31;
    const int wid  = tid >> 5;
    const int warpM = wid >> 1;
    const int warpN = wid & 1;
    const int row0 = blockIdx.y * 128;
    const int col0 = blockIdx.x * 64;
    const int n    = KP >> 5;

    auto issue = [&](int c, int buf) {
        uint32_t* As = smemu + buf * ASZ;
        uint32_t* Ws = smemu + STG * ASZ + buf * WSZ;
        const int koff = c * 32;
#pragma unroll
        for (int t = 0; t < 8; t++) {
            int j = tid + t * 128;
            int row = j >> 3, q = j & 7;
            int rg = row0 + row;
            bool v = rg < M;
            const float* src = A + (size_t)(v ? rg : 0) * KP + koff + q * 4;
            uint32_t d = (uint32_t)__cvta_generic_to_shared(&As[row * SA + q * 4]);
            int sz = v ? 16 : 0;
            asm volatile("cp.async.cg.shared.global [%0], [%1], 16, %2;"
                         :: "r"(d), "l"(src), "r"(sz));
        }
#pragma unroll
        for (int t = 0; t < 4; t++) {
            int j = tid + t * 128;
            int row = j >> 3, q = j & 7;
            const float* src = Wp + (size_t)(col0 + row) * KP + koff + q * 4;
            uint32_t d = (uint32_t)__cvta_generic_to_shared(&Ws[row * SA + q * 4]);
            asm volatile("cp.async.cg.shared.global [%0], [%1], 16, 16;"
                         :: "r"(d), "l"(src));
        }
        asm volatile("cp.async.commit_group;");
    };

    float acc[4][4][4];
#pragma unroll
    for (int i = 0; i < 4; i++)
#pragma unroll
        for (int j = 0; j < 4; j++)
#pragma unroll
            for (int q = 0; q < 4; q++) acc[i][j][q] = 0.f;

    issue(0, 0);
    if (n > 1) issue(1, 1);

    for (int c = 0; c < n; c++) {
        if (c + 1 < n) { asm volatile("cp.async.wait_group 1;"); }
        else           { asm volatile("cp.async.wait_group 0;"); }
        __syncthreads();
        if (c + 2 < n) issue(c + 2, (c + 2) % STG);

        const uint32_t* As = smemu + (c % STG) * ASZ;
        const uint32_t* Ws = smemu + STG * ASZ + (c % STG) * WSZ;
#pragma unroll
        for (int s = 0; s < 4; s++) {
            uint32_t a[4][4], b[4][2];
#pragma unroll
            for (int mf = 0; mf < 4; mf++) {
                int r = warpM * 64 + mf * 16 + (lane >> 2);
                uint2 lo = *reinterpret_cast<const uint2*>(
                    &As[r * SA + s * 8 + 2 * (lane & 3)]);
                uint2 hi = *reinterpret_cast<const uint2*>(
                    &As[(r + 8) * SA + s * 8 + 2 * (lane & 3)]);
                a[mf][0] = lo.x; a[mf][1] = hi.x; a[mf][2] = lo.y; a[mf][3] = hi.y;
            }
#pragma unroll
            for (int nf = 0; nf < 4; nf++) {
                int nn = warpN * 32 + nf * 8 + (lane >> 2);
                uint2 bb = *reinterpret_cast<const uint2*>(
                    &Ws[nn * SA + s * 8 + 2 * (lane & 3)]);
                b[nf][0] = bb.x; b[nf][1] = bb.y;
            }
#pragma unroll
            for (int mf = 0; mf < 4; mf++)
#pragma unroll
                for (int nf = 0; nf < 4; nf++)
                    mma8(acc[mf][nf], a[mf], b[nf]);
        }
    }

    // ---- epilogue (permuted column positions) ----
#pragma unroll
    for (int mf = 0; mf < 4; mf++) {
        int r0 = row0 + warpM * 64 + mf * 16 + (lane >> 2);
        int r1 = r0 + 8;
        bool v0 = r0 < M, v1 = r1 < M;
        int t0 = 0, t1 = 0;
        if (EPI == 1) {
            t0 = v0 ? ridx[r0] : 0;
            t1 = v1 ? ridx[r1] : 0;
        }
#pragma unroll
        for (int nf = 0; nf < 4; nf++) {
            int col = col0 + warpN * 32 + nf * 8 + 2 * (lane & 3);
            int pc0 = permcol(col), pc1 = permcol(col + 1);
            float c0 = acc[mf][nf][0], c1 = acc[mf][nf][1];
            float c2 = acc[mf][nf][2], c3 = acc[mf][nf][3];
            if (EPI == 0) {
                if (v0) {
                    Y[(size_t)r0 * NPAD + pc0] = rndtf(c0);
                    Y[(size_t)r0 * NPAD + pc1] = rndtf(c1);
                }
                if (v1) {
                    Y[(size_t)r1 * NPAD + pc0] = rndtf(c2);
                    Y[(size_t)r1 * NPAD + pc1] = rndtf(c3);
                }
            } else if (EPI == 1) {
                if (col < HID) {
                    float2 bsv = *reinterpret_cast<const float2*>(&biasp[col]);
                    if (v0) {
                        float a0 = addend[(size_t)r0 * NPAD + pc0];
                        float a1 = addend[(size_t)r0 * NPAD + pc1];
                        atomicAdd(accb + (size_t)t0 * NPAD + pc0,
                                  fmaxf(c0 + a0 + bsv.x, 0.f));
                        atomicAdd(accb + (size_t)t0 * NPAD + pc1,
                                  fmaxf(c1 + a1 + bsv.y, 0.f));
                    }
                    if (v1) {
                        float a2 = addend[(size_t)r1 * NPAD + pc0];
                        float a3 = addend[(size_t)r1 * NPAD + pc1];
                        atomicAdd(accb + (size_t)t1 * NPAD + pc0,
                                  fmaxf(c2 + a2 + bsv.x, 0.f));
                        atomicAdd(accb + (size_t)t1 * NPAD + pc1,
                                  fmaxf(c3 + a3 + bsv.y, 0.f));
                    }
                }
            } else { // EPI 2
                float2 bsv = *reinterpret_cast<const float2*>(&biasp[col]);
                c0 = fmaxf(c0 + bsv.x, 0.f); c1 = fmaxf(c1 + bsv.y, 0.f);
                c2 = fmaxf(c2 + bsv.x, 0.f); c3 = fmaxf(c3 + bsv.y, 0.f);
                if (v0) {
                    Y[(size_t)r0 * NPAD + pc0] = rndtf(c0);
                    Y[(size_t)r0 * NPAD + pc1] = rndtf(c1);
                }
                if (v1) {
                    Y[(size_t)r1 * NPAD + pc0] = rndtf(c2);
                    Y[(size_t)r1 * NPAD + pc1] = rndtf(c3);
                }
            }
        }
    }
}

// --------- index prep -------------------------------------------------------
__global__ void tgt_kernel(const int* __restrict__ b2a,
                           const int* __restrict__ b2revb,
                           int* __restrict__ tgt)
{
    int b = blockIdx.x * blockDim.x + threadIdx.x;
    if (b < NB) tgt[b] = b2a[b2revb[b]];
}

__global__ void bucket_kernel(const int* __restrict__ tgt,
                              int* __restrict__ cnt, int* __restrict__ bkt)
{
    int b = blockIdx.x * blockDim.x + threadIdx.x;
    if (b >= NB) return;
    int a = tgt[b];
    int s = atomicAdd(&cnt[a], 1);
    if (s < CAP) bkt[(size_t)a * CAP + s] = b;
}

// --------- gather (rounded): out[a] = rnd(sum over bucketed bonds of X[b]) -
__global__ void gather_kernel(const float* __restrict__ X,
                              const int* __restrict__ cnt,
                              const int* __restrict__ bkt,
                              float* __restrict__ out)
{
    int idx = blockIdx.x * blockDim.x + threadIdx.x;
    if (idx >= NA * CH76) return;
    int a = idx / CH76, c = idx % CH76;
    int n = cnt[a]; if (n > CAP) n = CAP;
    const int* bl = bkt + (size_t)a * CAP;
    float4 s = make_float4(0.f, 0.f, 0.f, 0.f);
    for (int j = 0; j < n; j++) {
        float4 v = reinterpret_cast<const float4*>(X + (size_t)bl[j] * NPAD)[c];
        s.x += v.x; s.y += v.y; s.z += v.z; s.w += v.w;
    }
    float4 r = make_float4(rndtf(s.x), rndtf(s.y), rndtf(s.z), rndtf(s.w));
    reinterpret_cast<float4*>(out + (size_t)a * NPAD)[c] = r;
}

// --------- fused final round: am2[a] = rnd(sum_b h3[b]), h3 on the fly -----
// h3[b] = relu(h0[b] + am[b2a[b]] - Y[b2revb[b]]), b in tgt-bucket of a.
__global__ void gather_final_kernel(const float* __restrict__ h0,
                                    const float* __restrict__ am,
                                    const float* __restrict__ Y,
                                    const int* __restrict__ b2a,
                                    const int* __restrict__ b2revb,
                                    const int* __restrict__ cnt,
                                    const int* __restrict__ bkt,
                                    float* __restrict__ am2)
{
    int idx = blockIdx.x * blockDim.x + threadIdx.x;
    if (idx >= NA * CH76) return;
    int a = idx / CH76, c = idx % CH76;
    int n = cnt[a]; if (n > CAP) n = CAP;
    const int* bl = bkt + (size_t)a * CAP;
    float4 s = make_float4(0.f, 0.f, 0.f, 0.f);
    for (int j = 0; j < n; j++) {
        int b = bl[j];
        float4 v0 = reinterpret_cast<const float4*>(h0 + (size_t)b * NPAD)[c];
        float4 va = reinterpret_cast<const float4*>(am + (size_t)b2a[b] * NPAD)[c];
        float4 vy = reinterpret_cast<const float4*>(Y + (size_t)b2revb[b] * NPAD)[c];
        s.x += fmaxf(v0.x + va.x - vy.x, 0.f);
        s.y += fmaxf(v0.y + va.y - vy.y, 0.f);
        s.z += fmaxf(v0.z + va.z - vy.z, 0.f);
        s.w += fmaxf(v0.w + va.w - vy.w, 0.f);
    }
    float4 r = make_float4(rndtf(s.x), rndtf(s.y), rndtf(s.z), rndtf(s.w));
    reinterpret_cast<float4*>(am2 + (size_t)a * NPAD)[c] = r;
}

// --------- pack A for h0 init: [NB x 160], permuted + rounded --------------
__global__ void pack_h0A(const float* __restrict__ fa, const float* __restrict__ fb,
                         const int* __restrict__ b2a, float* __restrict__ Ain)
{
    size_t idx = (size_t)blockIdx.x * blockDim.x + threadIdx.x;
    if (idx >= (size_t)NB * KP_I) return;
    int r = (int)(idx / KP_I), k = (int)(idx % KP_I);
    float v = 0.f;
    if (k < AF)            v = fa[(size_t)b2a[r] * AF + k];
    else if (k < AF + BFD) v = fb[(size_t)r * BFD + (k - AF)];
    Ain[(size_t)r * KP_I + permcol(k)] = rndtf(v);
}

// --------- packed atom features (permuted + rounded) -----------------------
__global__ void pack_faP(const float* __restrict__ fa, float* __restrict__ dst)
{
    size_t idx = (size_t)blockIdx.x * blockDim.x + threadIdx.x;
    if (idx >= (size_t)NA * KP_A) return;
    int a = (int)(idx / KP_A), k = (int)(idx % KP_A);
    float v = (k < AF) ? fa[(size_t)a * AF + k] : 0.f;
    dst[(size_t)a * KP_A + permcol(k)] = rndtf(v);
}

// --------- weight pad: src[rows x src_stride], cols [col0, col0+ncols) -----
__global__ void pad_W2(const float* __restrict__ src, int rows, int src_stride,
                       int col0, int ncols, int KP, float* __restrict__ dst)
{
    int idx = blockIdx.x * blockDim.x + threadIdx.x;
    if (idx >= NPAD * KP) return;
    int rp = idx / KP, k = idx % KP;
    float v = (rp < rows && k < ncols) ? src[(size_t)rp * src_stride + col0 + k] : 0.f;
    dst[(size_t)rp * KP + permcol(k)] = rndtf(v);
}

__global__ void pad_bias(const float* __restrict__ src, float* __restrict__ dst)
{
    int c = threadIdx.x + blockIdx.x * blockDim.x;
    if (c < NPAD) dst[c] = (c < HID) ? src[c] : 0.f;   // natural order
}

__global__ void round_kernel(float* __restrict__ x, int nelem)
{
    int i = blockIdx.x * blockDim.x + threadIdx.x;
    if (i < nelem) x[i] = rndtf(x[i]);
}

// --------- combine: h = rnd(relu(h0 + am[b2a] - Y[b2revb])) ----------------
__global__ void combine_kernel(const float* __restrict__ h0,
                               const float* __restrict__ amsg,
                               const float* __restrict__ Y,
                               const int* __restrict__ b2a,
                               const int* __restrict__ b2revb,
                               float* __restrict__ hout)
{
    size_t tid = (size_t)blockIdx.x * blockDim.x + threadIdx.x;
    if (tid >= (size_t)NB * CH76) return;
    int bond = (int)(tid / CH76);
    int c = (int)(tid % CH76);
    int a  = b2a[bond];
    int rb = b2revb[bond];
    float4 v0 = reinterpret_cast<const float4*>(h0   + (size_t)bond * NPAD)[c];
    float4 va = reinterpret_cast<const float4*>(amsg + (size_t)a    * NPAD)[c];
    float4 vy = reinterpret_cast<const float4*>(Y    + (size_t)rb   * NPAD)[c];
    float4 r;
    r.x = rndtf(fmaxf(v0.x + va.x - vy.x, 0.f));
    r.y = rndtf(fmaxf(v0.y + va.y - vy.y, 0.f));
    r.z = rndtf(fmaxf(v0.z + va.z - vy.z, 0.f));
    r.w = rndtf(fmaxf(v0.w + va.w - vy.w, 0.f));
    reinterpret_cast<float4*>(hout + (size_t)bond * NPAD)[c] = r;
}

// --------- final logits (o1 permuted; un-permute via invperm) --------------
__global__ void logits_kernel(const float* __restrict__ X,
                              const float* __restrict__ W2,
                              const float* __restrict__ b2,
                              float* __restrict__ out)
{
    int warp = (blockIdx.x * blockDim.x + threadIdx.x) >> 5;
    int lane = threadIdx.x & 31;
    if (warp >= NM) return;
    const float* x = X + (size_t)warp * NPAD;
    float acc[NTASK];
#pragma unroll
    for (int t = 0; t < NTASK; t++) acc[t] = 0.f;
    for (int p = lane; p < NPAD; p += 32) {
        int k = invperm(p);
        if (k >= HID) continue;
        float xv = x[p];
#pragma unroll
        for (int t = 0; t < NTASK; t++)
            acc[t] = fmaf(xv, W2[t * HID + k], acc[t]);
    }
#pragma unroll
    for (int t = 0; t < NTASK; t++) {
        float v = acc[t];
#pragma unroll
        for (int off = 16; off; off >>= 1)
            v += __shfl_down_sync(0xffffffffu, v, off);
        if (lane == 0) out[warp * NTASK + t] = v + b2[t];
    }
}

// ---------------- driver ----------------
extern "C" void kernel_launch(void* const* d_in, const int* in_sizes, int n_in,
                              void* d_out, int out_size)
{
    const float* f_atoms = (const float*)d_in[0];
    const float* f_bonds = (const float*)d_in[1];
    const int*   b2a     = (const int*)d_in[2];
    const int*   b2revb  = (const int*)d_in[3];
    const int*   mol_ids = (const int*)d_in[4];
    const float* W_i     = (const float*)d_in[5];
    const float* W_h     = (const float*)d_in[6];
    const float* W_o     = (const float*)d_in[7];
    const float* b_o     = (const float*)d_in[8];
    const float* W_r1    = (const float*)d_in[9];
    const float* b_r1    = (const float*)d_in[10];
    const float* W_r2    = (const float*)d_in[11];
    const float* b_r2    = (const float*)d_in[12];
    float* out = (float*)d_out;

    float *h0, *h, *Y, *am, *am2, *faP, *mol, *o1;
    float *WpI, *WpH, *Wo1, *Wo2, *WpR, *bO, *bR, *zb;
    int *tgt, *cnt, *bkt;
    cudaGetSymbolAddress((void**)&h0,  g_h0);
    cudaGetSymbolAddress((void**)&h,   g_h);
    cudaGetSymbolAddress((void**)&Y,   g_Y);
    cudaGetSymbolAddress((void**)&am,  g_am);
    cudaGetSymbolAddress((void**)&am2, g_am2);
    cudaGetSymbolAddress((void**)&faP, g_faP);
    cudaGetSymbolAddress((void**)&mol, g_mol);
    cudaGetSymbolAddress((void**)&o1,  g_o1);
    cudaGetSymbolAddress((void**)&WpI, g_WpI);
    cudaGetSymbolAddress((void**)&WpH, g_WpH);
    cudaGetSymbolAddress((void**)&Wo1, g_Wo1);
    cudaGetSymbolAddress((void**)&Wo2, g_Wo2);
    cudaGetSymbolAddress((void**)&WpR, g_WpR);
    cudaGetSymbolAddress((void**)&bO,  g_bO);
    cudaGetSymbolAddress((void**)&bR,  g_bR);
    cudaGetSymbolAddress((void**)&zb,  g_zb);
    cudaGetSymbolAddress((void**)&tgt, g_tgt);
    cudaGetSymbolAddress((void**)&cnt, g_cnt);
    cudaGetSymbolAddress((void**)&bkt, g_bkt);

    cudaFuncSetAttribute(mma_gemm<0>, cudaFuncAttributeMaxDynamicSharedMemorySize, SMEM_G);
    cudaFuncSetAttribute(mma_gemm<1>, cudaFuncAttributeMaxDynamicSharedMemorySize, SMEM_G);
    cudaFuncSetAttribute(mma_gemm<2>, cudaFuncAttributeMaxDynamicSharedMemorySize, SMEM_G);

    const dim3 blk(256);
    const dim3 gblk(128);

    // 0) indices + bucket-CSR + packed atom feats + padded weights/biases
    tgt_kernel<<<(NB + 255) / 256, blk>>>(b2a, b2revb, tgt);
    cudaMemsetAsync(cnt, 0, NA * sizeof(int));
    bucket_kernel<<<(NB + 255) / 256, blk>>>(tgt, cnt, bkt);
    pack_faP<<<(unsigned)(((size_t)NA * KP_A + 255) / 256), blk>>>(f_atoms, faP);
    pad_W2<<<(NPAD * KP_I + 255) / 256, blk>>>(W_i,  HID, AF + BFD, 0,  AF + BFD, KP_I, WpI);
    pad_W2<<<(NPAD * KP_H + 255) / 256, blk>>>(W_h,  HID, HID,      0,  HID,      KP_H, WpH);
    pad_W2<<<(NPAD * KP_A + 255) / 256, blk>>>(W_o,  HID, AF + HID, 0,  AF,       KP_A, Wo1);
    pad_W2<<<(NPAD * KP_H + 255) / 256, blk>>>(W_o,  HID, AF + HID, AF, HID,      KP_H, Wo2);
    pad_W2<<<(NPAD * KP_H + 255) / 256, blk>>>(W_r1, HID, HID,      0,  HID,      KP_H, WpR);
    pad_bias<<<2, 256>>>(b_o,  bO);
    pad_bias<<<2, 256>>>(b_r1, bR);

    // 1) h0 = relu(concat(f_atoms[b2a], f_bonds) @ W_i^T)
    //    pack into the (currently idle) h buffer, single GEMM
    {
        size_t n = (size_t)NB * KP_I;
        pack_h0A<<<(unsigned)((n + 255) / 256), blk>>>(f_atoms, f_bonds, b2a, h);
        dim3 g(NT, NB / 128);
        mma_gemm<2><<<g, gblk, SMEM_G>>>(h, NB, KP_I, WpI, zb, nullptr, nullptr,
                                         h0, nullptr);
    }

    // 2) message rounds:
    //    Y = h @ W_h^T;  am = rnd(bucket-gather(Y, tgt));
    //    rounds 0..1: h' = rnd(relu(h0 + am[b2a] - Y[b2revb]))
    //    round 2: fused into gather_final (h3 never materialized)
    const unsigned combB = (unsigned)(((size_t)NB * CH76 + 255) / 256);
    const unsigned gatB  = (unsigned)((NA * CH76 + 255) / 256);
    float* h_cur = h0;
    for (int d = 0; d < DEPTH; d++) {
        dim3 g(NT, NB / 128);
        mma_gemm<0><<<g, gblk, SMEM_G>>>(h_cur, NB, KP_H, WpH, nullptr, nullptr,
                                         nullptr, Y, nullptr);
        gather_kernel<<<gatB, blk>>>(Y, cnt, bkt, am);
        if (d < DEPTH - 1) {
            combine_kernel<<<combB, blk>>>(h0, am, Y, b2a, b2revb, h);
            h_cur = h;
        } else {
            gather_final_kernel<<<gatB, blk>>>(h0, am, Y, b2a, b2revb,
                                               cnt, bkt, am2);
        }
    }

    // 3) W_o readout via concat-split, fused with molecule pooling:
    //    tmp(am) = faP @ Wo1^T;  mol += relu(am2@Wo2^T + tmp + b_o) by mol_ids
    {
        dim3 g(NT, (NA + 127) / 128);
        mma_gemm<0><<<g, gblk, SMEM_G>>>(faP, NA, KP_A, Wo1, nullptr, nullptr,
                                         nullptr, am, nullptr);
        cudaMemsetAsync(mol, 0, (size_t)NM * NPAD * sizeof(float));
        mma_gemm<1><<<g, gblk, SMEM_G>>>(am2, NA, KP_H, Wo2, bO, mol_ids,
                                         am, nullptr, mol);
    }

    // 4) readout head
    round_kernel<<<(NM * NPAD + 255) / 256, blk>>>(mol, NM * NPAD);
    {
        dim3 g(NT, (NM + 127) / 128);
        mma_gemm<2><<<g, gblk, SMEM_G>>>(mol, NM, KP_H, WpR, bR, nullptr,
                                         nullptr, o1, nullptr);
    }
    logits_kernel<<<(NM * 32 + 255) / 256, blk>>>(o1, W_r2, b_r2, out);
}